// round 1
// baseline (speedup 1.0000x reference)
#include <cuda_runtime.h>

#define BATCH   128
#define NUM_IN  4096
#define NLEV    8
#define H       32768
#define KFAN    32
#define NOUT    256
#define KOUT    64
#define SCALE   4.9f

#define NODES   (NUM_IN + NLEV * H)   // 266240 nodes stored node-major

// Node-major activation buffer: buf[node * BATCH + b].  ~130 MB static scratch.
__device__ float g_buf[(size_t)NODES * BATCH];

__device__ __forceinline__ float fast_sigmoid(float x) {
    return 1.0f / (1.0f + __expf(-x));
}

// ---------------------------------------------------------------------------
// Kernel 1: transpose x [B, NUM_IN] -> g_buf[node*B + b] for node < NUM_IN.
// One block per input node, 128 threads = batch. Writes coalesced.
// ---------------------------------------------------------------------------
__global__ void init_buf_kernel(const float* __restrict__ x) {
    const int n = blockIdx.x;       // 0..NUM_IN-1
    const int b = threadIdx.x;      // 0..127
    g_buf[(size_t)n * BATCH + b] = __ldg(&x[(size_t)b * NUM_IN + n]);
}

// ---------------------------------------------------------------------------
// Kernel 2: one topological level. Each block: 128 threads (= batch lane),
// processes 4 hidden units with interleaved accumulators (MLP=4).
// w/idx pointers are pre-offset to this level. base = NUM_IN + l*H.
// ---------------------------------------------------------------------------
__global__ void __launch_bounds__(BATCH) level_kernel(
    const float* __restrict__ w,    // [H, K] for this level
    const int*   __restrict__ idx,  // [H, K] for this level
    int base)                       // first output node id of this level
{
    const int b  = threadIdx.x;
    const int h0 = blockIdx.x * 4;

    const int*   ip = idx + (size_t)h0 * KFAN;
    const float* wp = w   + (size_t)h0 * KFAN;

    float acc0 = 0.f, acc1 = 0.f, acc2 = 0.f, acc3 = 0.f;

#pragma unroll
    for (int k = 0; k < KFAN; ++k) {
        const int i0 = __ldg(ip + 0 * KFAN + k);
        const int i1 = __ldg(ip + 1 * KFAN + k);
        const int i2 = __ldg(ip + 2 * KFAN + k);
        const int i3 = __ldg(ip + 3 * KFAN + k);

        const float w0 = __ldg(wp + 0 * KFAN + k);
        const float w1 = __ldg(wp + 1 * KFAN + k);
        const float w2 = __ldg(wp + 2 * KFAN + k);
        const float w3 = __ldg(wp + 3 * KFAN + k);

        const float v0 = __ldg(&g_buf[(size_t)i0 * BATCH + b]);
        const float v1 = __ldg(&g_buf[(size_t)i1 * BATCH + b]);
        const float v2 = __ldg(&g_buf[(size_t)i2 * BATCH + b]);
        const float v3 = __ldg(&g_buf[(size_t)i3 * BATCH + b]);

        acc0 = fmaf(w0, v0, acc0);
        acc1 = fmaf(w1, v1, acc1);
        acc2 = fmaf(w2, v2, acc2);
        acc3 = fmaf(w3, v3, acc3);
    }

    g_buf[(size_t)(base + h0 + 0) * BATCH + b] = fast_sigmoid(SCALE * acc0);
    g_buf[(size_t)(base + h0 + 1) * BATCH + b] = fast_sigmoid(SCALE * acc1);
    g_buf[(size_t)(base + h0 + 2) * BATCH + b] = fast_sigmoid(SCALE * acc2);
    g_buf[(size_t)(base + h0 + 3) * BATCH + b] = fast_sigmoid(SCALE * acc3);
}

// ---------------------------------------------------------------------------
// Kernel 3: output layer. One block per output unit (256 blocks),
// 128 threads = batch. out[b*NOUT + o] per reference layout [B, O].
// ---------------------------------------------------------------------------
__global__ void __launch_bounds__(BATCH) output_kernel(
    const float* __restrict__ w_out,   // [O, KO]
    const int*   __restrict__ idx_out, // [O, KO]
    float*       __restrict__ out)     // [B, O]
{
    const int b = threadIdx.x;
    const int o = blockIdx.x;

    const int*   ip = idx_out + (size_t)o * KOUT;
    const float* wp = w_out   + (size_t)o * KOUT;

    float acc = 0.f;
#pragma unroll
    for (int k = 0; k < KOUT; ++k) {
        const int   i  = __ldg(ip + k);
        const float wv = __ldg(wp + k);
        acc = fmaf(wv, __ldg(&g_buf[(size_t)i * BATCH + b]), acc);
    }

    out[(size_t)b * NOUT + o] = fast_sigmoid(SCALE * acc);
}

// ---------------------------------------------------------------------------
// Launch: 1 init + 8 level + 1 output kernels, all graph-capturable.
// Input order (metadata): x, w_hidden, w_out, idx_hidden, idx_out.
// ---------------------------------------------------------------------------
extern "C" void kernel_launch(void* const* d_in, const int* in_sizes, int n_in,
                              void* d_out, int out_size) {
    const float* x        = (const float*)d_in[0];
    const float* w_hidden = (const float*)d_in[1];  // [L, H, K]
    const float* w_out    = (const float*)d_in[2];  // [O, KO]
    const int*   idx_hid  = (const int*)  d_in[3];  // [L, H, K]
    const int*   idx_out  = (const int*)  d_in[4];  // [O, KO]
    float*       out      = (float*)d_out;          // [B, O]

    init_buf_kernel<<<NUM_IN, BATCH>>>(x);

    for (int l = 0; l < NLEV; ++l) {
        const float* wl = w_hidden + (size_t)l * H * KFAN;
        const int*   il = idx_hid  + (size_t)l * H * KFAN;
        level_kernel<<<H / 4, BATCH>>>(wl, il, NUM_IN + l * H);
    }

    output_kernel<<<NOUT, BATCH>>>(w_out, idx_out, out);
}

// round 2
// speedup vs baseline: 1.4850x; 1.4850x over previous
#include <cuda_runtime.h>

#define BATCH   128
#define NUM_IN  4096
#define NLEV    8
#define H       32768
#define KFAN    32
#define NOUT    256
#define KOUT    64
#define SCALE   4.9f

#define NODES   (NUM_IN + NLEV * H)   // 266240 nodes, stored node-major

// Node-major activation buffer: buf[node * BATCH + b].  ~130 MB static scratch.
__device__ float g_buf[(size_t)NODES * BATCH];

__device__ __forceinline__ float fast_sigmoid(float x) {
    return 1.0f / (1.0f + __expf(-x));
}

// ---------------------------------------------------------------------------
// Kernel 1: transpose x [B, NUM_IN] -> g_buf[node*B + b] for node < NUM_IN.
// 2 MB one-shot transpose; negligible either orientation.
// ---------------------------------------------------------------------------
__global__ void init_buf_kernel(const float* __restrict__ x) {
    const int n = blockIdx.x;       // 0..NUM_IN-1
    const int b = threadIdx.x;      // 0..127
    g_buf[(size_t)n * BATCH + b] = __ldg(&x[(size_t)b * NUM_IN + n]);
}

// ---------------------------------------------------------------------------
// Kernel 2: one topological level.
// One warp per hidden unit; each thread owns a batch QUAD (float4).
// Per warp per unit: 8 int4 + 8 float4 (idx/w, uniform) + 32 float4 gathers
// + 1 float4 store  ==  48 LDG + 1 STG  (vs 384 scalar LDGs before).
// ---------------------------------------------------------------------------
__global__ void __launch_bounds__(BATCH, 8) level_kernel(
    const float* __restrict__ w,    // [H, K] for this level
    const int*   __restrict__ idx,  // [H, K] for this level
    int base)                       // first output node id of this level
{
    const int lane = threadIdx.x & 31;   // batch quad: lanes 4*lane .. 4*lane+3
    const int wid  = threadIdx.x >> 5;   // warp -> unit within block
    const int h    = blockIdx.x * 4 + wid;

    const float4* __restrict__ buf4 = (const float4*)g_buf;   // [node][32] quads

    const int4*   ip4 = (const int4*)  (idx + (size_t)h * KFAN);
    const float4* wp4 = (const float4*)(w   + (size_t)h * KFAN);

    float ax = 0.f, ay = 0.f, az = 0.f, aw = 0.f;

#pragma unroll
    for (int kk = 0; kk < KFAN / 4; ++kk) {
        const int4   i4 = __ldg(ip4 + kk);   // warp-uniform broadcast
        const float4 w4 = __ldg(wp4 + kk);

        float4 v0 = __ldg(buf4 + (size_t)i4.x * 32 + lane);
        float4 v1 = __ldg(buf4 + (size_t)i4.y * 32 + lane);
        float4 v2 = __ldg(buf4 + (size_t)i4.z * 32 + lane);
        float4 v3 = __ldg(buf4 + (size_t)i4.w * 32 + lane);

        ax = fmaf(w4.x, v0.x, ax); ay = fmaf(w4.x, v0.y, ay);
        az = fmaf(w4.x, v0.z, az); aw = fmaf(w4.x, v0.w, aw);

        ax = fmaf(w4.y, v1.x, ax); ay = fmaf(w4.y, v1.y, ay);
        az = fmaf(w4.y, v1.z, az); aw = fmaf(w4.y, v1.w, aw);

        ax = fmaf(w4.z, v2.x, ax); ay = fmaf(w4.z, v2.y, ay);
        az = fmaf(w4.z, v2.z, az); aw = fmaf(w4.z, v2.w, aw);

        ax = fmaf(w4.w, v3.x, ax); ay = fmaf(w4.w, v3.y, ay);
        az = fmaf(w4.w, v3.z, az); aw = fmaf(w4.w, v3.w, aw);
    }

    float4 r;
    r.x = fast_sigmoid(SCALE * ax);
    r.y = fast_sigmoid(SCALE * ay);
    r.z = fast_sigmoid(SCALE * az);
    r.w = fast_sigmoid(SCALE * aw);

    ((float4*)g_buf)[(size_t)(base + h) * 32 + lane] = r;
}

// ---------------------------------------------------------------------------
// Kernel 3: output layer. One warp per output unit, float4 batch quads.
// 256 units -> 64 blocks of 4 warps.
// ---------------------------------------------------------------------------
__global__ void __launch_bounds__(BATCH) output_kernel(
    const float* __restrict__ w_out,   // [O, KO]
    const int*   __restrict__ idx_out, // [O, KO]
    float*       __restrict__ out)     // [B, O]
{
    const int lane = threadIdx.x & 31;
    const int wid  = threadIdx.x >> 5;
    const int o    = blockIdx.x * 4 + wid;

    const float4* __restrict__ buf4 = (const float4*)g_buf;

    const int4*   ip4 = (const int4*)  (idx_out + (size_t)o * KOUT);
    const float4* wp4 = (const float4*)(w_out   + (size_t)o * KOUT);

    float ax = 0.f, ay = 0.f, az = 0.f, aw = 0.f;

#pragma unroll
    for (int kk = 0; kk < KOUT / 4; ++kk) {
        const int4   i4 = __ldg(ip4 + kk);
        const float4 w4 = __ldg(wp4 + kk);

        float4 v0 = __ldg(buf4 + (size_t)i4.x * 32 + lane);
        float4 v1 = __ldg(buf4 + (size_t)i4.y * 32 + lane);
        float4 v2 = __ldg(buf4 + (size_t)i4.z * 32 + lane);
        float4 v3 = __ldg(buf4 + (size_t)i4.w * 32 + lane);

        ax = fmaf(w4.x, v0.x, ax); ay = fmaf(w4.x, v0.y, ay);
        az = fmaf(w4.x, v0.z, az); aw = fmaf(w4.x, v0.w, aw);
        ax = fmaf(w4.y, v1.x, ax); ay = fmaf(w4.y, v1.y, ay);
        az = fmaf(w4.y, v1.z, az); aw = fmaf(w4.y, v1.w, aw);
        ax = fmaf(w4.z, v2.x, ax); ay = fmaf(w4.z, v2.y, ay);
        az = fmaf(w4.z, v2.z, az); aw = fmaf(w4.z, v2.w, aw);
        ax = fmaf(w4.w, v3.x, ax); ay = fmaf(w4.w, v3.y, ay);
        az = fmaf(w4.w, v3.z, az); aw = fmaf(w4.w, v3.w, aw);
    }

    // out is [B, O]: batch lanes 4*lane..4*lane+3, column o.
    const int b0 = lane * 4;
    out[(size_t)(b0 + 0) * NOUT + o] = fast_sigmoid(SCALE * ax);
    out[(size_t)(b0 + 1) * NOUT + o] = fast_sigmoid(SCALE * ay);
    out[(size_t)(b0 + 2) * NOUT + o] = fast_sigmoid(SCALE * az);
    out[(size_t)(b0 + 3) * NOUT + o] = fast_sigmoid(SCALE * aw);
}

// ---------------------------------------------------------------------------
// Launch: 1 init + 8 level + 1 output kernels, all graph-capturable.
// Input order (metadata): x, w_hidden, w_out, idx_hidden, idx_out.
// ---------------------------------------------------------------------------
extern "C" void kernel_launch(void* const* d_in, const int* in_sizes, int n_in,
                              void* d_out, int out_size) {
    const float* x        = (const float*)d_in[0];
    const float* w_hidden = (const float*)d_in[1];  // [L, H, K]
    const float* w_out    = (const float*)d_in[2];  // [O, KO]
    const int*   idx_hid  = (const int*)  d_in[3];  // [L, H, K]
    const int*   idx_out  = (const int*)  d_in[4];  // [O, KO]
    float*       out      = (float*)d_out;          // [B, O]

    init_buf_kernel<<<NUM_IN, BATCH>>>(x);

    for (int l = 0; l < NLEV; ++l) {
        const float* wl = w_hidden + (size_t)l * H * KFAN;
        const int*   il = idx_hid  + (size_t)l * H * KFAN;
        level_kernel<<<H / 4, BATCH>>>(wl, il, NUM_IN + l * H);
    }

    output_kernel<<<NOUT / 4, BATCH>>>(w_out, idx_out, out);
}

// round 3
// speedup vs baseline: 2.6226x; 1.7661x over previous
#include <cuda_runtime.h>
#include <cuda_fp16.h>

#define BATCH   128
#define NUM_IN  4096
#define NLEV    8
#define H       32768
#define KFAN    32
#define NOUT    256
#define KOUT    64
#define SCALE   4.9f

#define NODES   (NUM_IN + NLEV * H)   // 266240 nodes, stored node-major

// Node-major activation buffer in fp16: buf[node * BATCH + b].  ~65 MB scratch.
__device__ __half g_buf[(size_t)NODES * BATCH];

__device__ __forceinline__ float fast_sigmoid(float x) {
    return 1.0f / (1.0f + __expf(-x));
}

// Gather 4 consecutive batch halves (8B) for node n at batch-quad `lane`.
__device__ __forceinline__ float4 gather4(const __half* __restrict__ buf, int n, int lane) {
    const uint2 raw = __ldg((const uint2*)(buf + (size_t)n * BATCH + lane * 4));
    const __half2 h01 = *(const __half2*)&raw.x;
    const __half2 h23 = *(const __half2*)&raw.y;
    const float2 f01 = __half22float2(h01);
    const float2 f23 = __half22float2(h23);
    return make_float4(f01.x, f01.y, f23.x, f23.y);
}

// ---------------------------------------------------------------------------
// Kernel 1: transpose+quantize x [B, NUM_IN] -> g_buf[n*B + b] (fp16).
// ---------------------------------------------------------------------------
__global__ void init_buf_kernel(const float* __restrict__ x) {
    const int n = blockIdx.x;       // 0..NUM_IN-1
    const int b = threadIdx.x;      // 0..127
    g_buf[(size_t)n * BATCH + b] = __float2half_rn(__ldg(&x[(size_t)b * NUM_IN + n]));
}

// ---------------------------------------------------------------------------
// Kernel 2: one topological level.
// One warp per hidden unit; each lane owns a batch quad (4 halves = 8B gather).
// Per warp per unit: 8 int4 + 8 float4 (uniform) + 32 x 8B gathers + 1 x 8B store.
// ---------------------------------------------------------------------------
__global__ void __launch_bounds__(BATCH, 8) level_kernel(
    const float* __restrict__ w,    // [H, K] for this level
    const int*   __restrict__ idx,  // [H, K] for this level
    int base)                       // first output node id of this level
{
    const int lane = threadIdx.x & 31;   // batch quad: 4*lane .. 4*lane+3
    const int wid  = threadIdx.x >> 5;
    const int h    = blockIdx.x * 4 + wid;

    const int4*   ip4 = (const int4*)  (idx + (size_t)h * KFAN);
    const float4* wp4 = (const float4*)(w   + (size_t)h * KFAN);

    float ax = 0.f, ay = 0.f, az = 0.f, aw = 0.f;

#pragma unroll
    for (int kk = 0; kk < KFAN / 4; ++kk) {
        const int4   i4 = __ldg(ip4 + kk);   // warp-uniform broadcast
        const float4 w4 = __ldg(wp4 + kk);

        const float4 v0 = gather4(g_buf, i4.x, lane);
        const float4 v1 = gather4(g_buf, i4.y, lane);
        const float4 v2 = gather4(g_buf, i4.z, lane);
        const float4 v3 = gather4(g_buf, i4.w, lane);

        ax = fmaf(w4.x, v0.x, ax); ay = fmaf(w4.x, v0.y, ay);
        az = fmaf(w4.x, v0.z, az); aw = fmaf(w4.x, v0.w, aw);

        ax = fmaf(w4.y, v1.x, ax); ay = fmaf(w4.y, v1.y, ay);
        az = fmaf(w4.y, v1.z, az); aw = fmaf(w4.y, v1.w, aw);

        ax = fmaf(w4.z, v2.x, ax); ay = fmaf(w4.z, v2.y, ay);
        az = fmaf(w4.z, v2.z, az); aw = fmaf(w4.z, v2.w, aw);

        ax = fmaf(w4.w, v3.x, ax); ay = fmaf(w4.w, v3.y, ay);
        az = fmaf(w4.w, v3.z, az); aw = fmaf(w4.w, v3.w, aw);
    }

    const __half2 r01 = __floats2half2_rn(fast_sigmoid(SCALE * ax),
                                          fast_sigmoid(SCALE * ay));
    const __half2 r23 = __floats2half2_rn(fast_sigmoid(SCALE * az),
                                          fast_sigmoid(SCALE * aw));
    uint2 packed;
    packed.x = *(const unsigned int*)&r01;
    packed.y = *(const unsigned int*)&r23;
    *(uint2*)(g_buf + (size_t)(base + h) * BATCH + lane * 4) = packed;
}

// ---------------------------------------------------------------------------
// Kernel 3: output layer. One warp per output unit, batch quads. fp32 out.
// ---------------------------------------------------------------------------
__global__ void __launch_bounds__(BATCH) output_kernel(
    const float* __restrict__ w_out,   // [O, KO]
    const int*   __restrict__ idx_out, // [O, KO]
    float*       __restrict__ out)     // [B, O]
{
    const int lane = threadIdx.x & 31;
    const int wid  = threadIdx.x >> 5;
    const int o    = blockIdx.x * 4 + wid;

    const int4*   ip4 = (const int4*)  (idx_out + (size_t)o * KOUT);
    const float4* wp4 = (const float4*)(w_out   + (size_t)o * KOUT);

    float ax = 0.f, ay = 0.f, az = 0.f, aw = 0.f;

#pragma unroll
    for (int kk = 0; kk < KOUT / 4; ++kk) {
        const int4   i4 = __ldg(ip4 + kk);
        const float4 w4 = __ldg(wp4 + kk);

        const float4 v0 = gather4(g_buf, i4.x, lane);
        const float4 v1 = gather4(g_buf, i4.y, lane);
        const float4 v2 = gather4(g_buf, i4.z, lane);
        const float4 v3 = gather4(g_buf, i4.w, lane);

        ax = fmaf(w4.x, v0.x, ax); ay = fmaf(w4.x, v0.y, ay);
        az = fmaf(w4.x, v0.z, az); aw = fmaf(w4.x, v0.w, aw);
        ax = fmaf(w4.y, v1.x, ax); ay = fmaf(w4.y, v1.y, ay);
        az = fmaf(w4.y, v1.z, az); aw = fmaf(w4.y, v1.w, aw);
        ax = fmaf(w4.z, v2.x, ax); ay = fmaf(w4.z, v2.y, ay);
        az = fmaf(w4.z, v2.z, az); aw = fmaf(w4.z, v2.w, aw);
        ax = fmaf(w4.w, v3.x, ax); ay = fmaf(w4.w, v3.y, ay);
        az = fmaf(w4.w, v3.z, az); aw = fmaf(w4.w, v3.w, aw);
    }

    // out is [B, O] fp32: batch rows 4*lane..4*lane+3, column o.
    const int b0 = lane * 4;
    out[(size_t)(b0 + 0) * NOUT + o] = fast_sigmoid(SCALE * ax);
    out[(size_t)(b0 + 1) * NOUT + o] = fast_sigmoid(SCALE * ay);
    out[(size_t)(b0 + 2) * NOUT + o] = fast_sigmoid(SCALE * az);
    out[(size_t)(b0 + 3) * NOUT + o] = fast_sigmoid(SCALE * aw);
}

// ---------------------------------------------------------------------------
// Launch: 1 init + 8 level + 1 output kernels, all graph-capturable.
// Input order (metadata): x, w_hidden, w_out, idx_hidden, idx_out.
// ---------------------------------------------------------------------------
extern "C" void kernel_launch(void* const* d_in, const int* in_sizes, int n_in,
                              void* d_out, int out_size) {
    const float* x        = (const float*)d_in[0];
    const float* w_hidden = (const float*)d_in[1];  // [L, H, K]
    const float* w_out    = (const float*)d_in[2];  // [O, KO]
    const int*   idx_hid  = (const int*)  d_in[3];  // [L, H, K]
    const int*   idx_out  = (const int*)  d_in[4];  // [O, KO]
    float*       out      = (float*)d_out;          // [B, O]

    init_buf_kernel<<<NUM_IN, BATCH>>>(x);

    for (int l = 0; l < NLEV; ++l) {
        const float* wl = w_hidden + (size_t)l * H * KFAN;
        const int*   il = idx_hid  + (size_t)l * H * KFAN;
        level_kernel<<<H / 4, BATCH>>>(wl, il, NUM_IN + l * H);
    }

    output_kernel<<<NOUT / 4, BATCH>>>(w_out, idx_out, out);
}